// round 1
// baseline (speedup 1.0000x reference)
#include <cuda_runtime.h>
#include <cstddef>

// Problem constants: B=4, S=4096, D=512
#define ROWS_TOTAL 16384      // B*S
#define DIMD 512
#define CCHUNK 128            // chunk length
#define NCHUNKS 128           // total chunks = 4 batches * 32 chunks
#define CHUNKS_PER_BATCH 32

// ---------------- scratch (static device globals; no allocation) ----------------
__device__ float g_q[(size_t)ROWS_TOTAL * DIMD];
__device__ float g_k[(size_t)ROWS_TOTAL * DIMD];
__device__ float g_v[(size_t)ROWS_TOTAL * DIMD];
__device__ float g_y[(size_t)ROWS_TOTAL * DIMD];
__device__ float g_state[(size_t)NCHUNKS * DIMD * DIMD];     // per-chunk S_c, then exclusive prefix P_c
__device__ float g_scores[(size_t)NCHUNKS * CCHUNK * CCHUNK]; // masked intra-chunk scores

// ---------------- generic fp32 GEMM: C[M,N] (+)= op(A) * op(B) ----------------
// TA=0: A is [M,K] row-major. TA=1: A is [K,M] row-major (computes A^T * B).
// TB=0: B is [K,N] row-major. TB=1: B is [N,K] row-major (computes A * B^T).
// ACCUM=1: C += result. Per-z strides for batched use. All dims multiples of 128/16.
template <int TA, int TB, int ACCUM>
__global__ __launch_bounds__(256)
void la_gemm128(const float* __restrict__ Ab, const float* __restrict__ Bb,
                float* __restrict__ Cb, int M, int N, int K,
                long sA, long sB, long sC)
{
    __shared__ float As[16][128];
    __shared__ float Bs[16][128];

    const int tid = threadIdx.x;
    const int ty = tid >> 4;      // 0..15
    const int tx = tid & 15;      // 0..15
    const int bn = blockIdx.x * 128;
    const int bm = blockIdx.y * 128;
    const long z = blockIdx.z;

    const float* __restrict__ A = Ab + z * sA;
    const float* __restrict__ B = Bb + z * sB;
    float* __restrict__ C = Cb + z * sC;

    float acc[8][8];
#pragma unroll
    for (int i = 0; i < 8; i++)
#pragma unroll
        for (int j = 0; j < 8; j++) acc[i][j] = 0.0f;

    for (int k0 = 0; k0 < K; k0 += 16) {
#pragma unroll
        for (int r = 0; r < 8; r++) {
            int e = tid + 256 * r;   // 0..2047
            if (TA == 0) {
                int m = e >> 4, kk = e & 15;
                As[kk][m] = A[(size_t)(bm + m) * K + (k0 + kk)];
            } else {
                int kk = e >> 7, m = e & 127;
                As[kk][m] = A[(size_t)(k0 + kk) * M + (bm + m)];
            }
            if (TB == 0) {
                int kk = e >> 7, n = e & 127;
                Bs[kk][n] = B[(size_t)(k0 + kk) * N + (bn + n)];
            } else {
                int n = e >> 4, kk = e & 15;
                Bs[kk][n] = B[(size_t)(bn + n) * K + (k0 + kk)];
            }
        }
        __syncthreads();
#pragma unroll
        for (int kk = 0; kk < 16; kk++) {
            float a[8], b[8];
#pragma unroll
            for (int i = 0; i < 8; i++) a[i] = As[kk][ty * 8 + i];
#pragma unroll
            for (int j = 0; j < 8; j++) b[j] = Bs[kk][tx * 8 + j];
#pragma unroll
            for (int i = 0; i < 8; i++)
#pragma unroll
                for (int j = 0; j < 8; j++) acc[i][j] += a[i] * b[j];
        }
        __syncthreads();
    }

#pragma unroll
    for (int i = 0; i < 8; i++) {
        int r = bm + ty * 8 + i;
#pragma unroll
        for (int j = 0; j < 8; j++) {
            int c = bn + tx * 8 + j;
            if (ACCUM) C[(size_t)r * N + c] += acc[i][j];
            else       C[(size_t)r * N + c]  = acc[i][j];
        }
    }
}

// ---------------- masked intra-chunk scores: S[t][s] = (s<=t) ? q_t . k_s : 0 ----
__global__ __launch_bounds__(256)
void la_scores(const float* __restrict__ q, const float* __restrict__ k,
               float* __restrict__ scores)
{
    const int z = blockIdx.x;  // chunk id
    const float* __restrict__ Q = q + (size_t)z * CCHUNK * DIMD;
    const float* __restrict__ Kp = k + (size_t)z * CCHUNK * DIMD;
    float* __restrict__ Sc = scores + (size_t)z * CCHUNK * CCHUNK;

    __shared__ float Qs[16][128];
    __shared__ float Ks[16][128];

    const int tid = threadIdx.x;
    const int ty = tid >> 4, tx = tid & 15;

    float acc[8][8];
#pragma unroll
    for (int i = 0; i < 8; i++)
#pragma unroll
        for (int j = 0; j < 8; j++) acc[i][j] = 0.0f;

    for (int k0 = 0; k0 < DIMD; k0 += 16) {
#pragma unroll
        for (int r = 0; r < 8; r++) {
            int e = tid + 256 * r;
            int m = e >> 4, kk = e & 15;
            Qs[kk][m] = Q[(size_t)m * DIMD + (k0 + kk)];
            Ks[kk][m] = Kp[(size_t)m * DIMD + (k0 + kk)];
        }
        __syncthreads();
#pragma unroll
        for (int kk = 0; kk < 16; kk++) {
            float a[8], b[8];
#pragma unroll
            for (int i = 0; i < 8; i++) a[i] = Qs[kk][ty * 8 + i];
#pragma unroll
            for (int j = 0; j < 8; j++) b[j] = Ks[kk][tx * 8 + j];
#pragma unroll
            for (int i = 0; i < 8; i++)
#pragma unroll
                for (int j = 0; j < 8; j++) acc[i][j] += a[i] * b[j];
        }
        __syncthreads();
    }

#pragma unroll
    for (int i = 0; i < 8; i++) {
        int r = ty * 8 + i;
#pragma unroll
        for (int j = 0; j < 8; j++) {
            int c = tx * 8 + j;
            Sc[(size_t)r * CCHUNK + c] = (c <= r) ? acc[i][j] : 0.0f;
        }
    }
}

// ---------------- exclusive prefix over chunks (in-place on g_state) ----------------
__global__ __launch_bounds__(256)
void la_prefix(float* __restrict__ state)
{
    const int e = blockIdx.x * 256 + threadIdx.x;  // element within [D*D)
    const int b = blockIdx.y;                      // batch
    float run = 0.0f;
    for (int c = 0; c < CHUNKS_PER_BATCH; c++) {
        size_t idx = ((size_t)(b * CHUNKS_PER_BATCH + c)) * (DIMD * DIMD) + e;
        float t = state[idx];
        state[idx] = run;
        run += t;
    }
}

// ---------------- launcher ----------------
extern "C" void kernel_launch(void* const* d_in, const int* in_sizes, int n_in,
                              void* d_out, int out_size)
{
    // Identify x by size (B*S*D); remaining inputs are Wq, Wk, Wv, Wo in order.
    int xi = 0;
    for (int i = 0; i < n_in; i++) {
        if (in_sizes[i] == ROWS_TOTAL * DIMD) { xi = i; break; }
    }
    const float* W[4];
    int wi = 0;
    for (int i = 0; i < n_in && wi < 4; i++) {
        if (i == xi) continue;
        W[wi++] = (const float*)d_in[i];
    }
    const float* x  = (const float*)d_in[xi];
    const float* Wq = W[0];
    const float* Wk = W[1];
    const float* Wv = W[2];
    const float* Wo = W[3];
    float* out = (float*)d_out;

    float *q, *k, *v, *y, *st, *sc;
    cudaGetSymbolAddress((void**)&q,  g_q);
    cudaGetSymbolAddress((void**)&k,  g_k);
    cudaGetSymbolAddress((void**)&v,  g_v);
    cudaGetSymbolAddress((void**)&y,  g_y);
    cudaGetSymbolAddress((void**)&st, g_state);
    cudaGetSymbolAddress((void**)&sc, g_scores);

    const long CH = (long)CCHUNK * DIMD;     // 128*512 elements per chunk of q/k/v/y
    const long ST = (long)DIMD * DIMD;       // 512*512 per-chunk state
    const long SS = (long)CCHUNK * CCHUNK;   // 128*128 scores per chunk

    // 1) projections: q/k/v = x @ W  (M=16384, N=512, K=512)
    la_gemm128<0,0,0><<<dim3(4,128,1), 256>>>(x, Wq, q, ROWS_TOTAL, DIMD, DIMD, 0, 0, 0);
    la_gemm128<0,0,0><<<dim3(4,128,1), 256>>>(x, Wk, k, ROWS_TOTAL, DIMD, DIMD, 0, 0, 0);
    la_gemm128<0,0,0><<<dim3(4,128,1), 256>>>(x, Wv, v, ROWS_TOTAL, DIMD, DIMD, 0, 0, 0);

    // 2) per-chunk state S_c = V_c^T K_c  (M=512, N=512, K=128), z = chunk
    la_gemm128<1,0,0><<<dim3(4,4,NCHUNKS), 256>>>(v, k, st, DIMD, DIMD, CCHUNK, CH, CH, ST);

    // 3) exclusive prefix over chunks within each batch (in-place)
    la_prefix<<<dim3(DIMD * DIMD / 256, 4), 256>>>(st);

    // 4) inter-chunk output: Y_c = Q_c @ P_c^T  (M=128, N=512, K=512)
    la_gemm128<0,1,0><<<dim3(4,1,NCHUNKS), 256>>>(q, st, y, CCHUNK, DIMD, DIMD, CH, ST, CH);

    // 5) intra-chunk masked scores
    la_scores<<<NCHUNKS, 256>>>(q, k, sc);

    // 6) Y_c += scores_c @ V_c  (M=128, N=512, K=128)
    la_gemm128<0,0,1><<<dim3(4,1,NCHUNKS), 256>>>(sc, v, y, CCHUNK, DIMD, CCHUNK, SS, CH, CH);

    // 7) out = Y @ Wo  (M=16384, N=512, K=512)
    la_gemm128<0,0,0><<<dim3(4,128,1), 256>>>(y, Wo, out, ROWS_TOTAL, DIMD, DIMD, 0, 0, 0);
}

// round 3
// speedup vs baseline: 3.4168x; 3.4168x over previous
#include <cuda_runtime.h>
#include <cuda_bf16.h>
#include <cstdint>
#include <cstddef>

// Problem constants: B=4, S=4096, D=512
#define ROWS_TOTAL 16384
#define DIMD 512
#define CCHUNK 128
#define NCHUNKS 128
#define CHUNKS_PER_BATCH 32

#define NE ((size_t)ROWS_TOTAL * DIMD)            // 8,388,608 elements
#define STN ((size_t)NCHUNKS * DIMD * DIMD)       // 33,554,432
#define SCN ((size_t)NCHUNKS * CCHUNK * CCHUNK)   // 2,097,152

// ---------------------------------------------------------------------------
// Scratch planes (static device globals; no allocation)
// ---------------------------------------------------------------------------
__device__ __align__(16) __nv_bfloat16 g_xh[NE], g_xl[NE];
__device__ __align__(16) __nv_bfloat16 g_qh[NE], g_ql[NE];
__device__ __align__(16) __nv_bfloat16 g_kh[NE], g_kl[NE];
__device__ __align__(16) __nv_bfloat16 g_vh[NE], g_vl[NE];
__device__ __align__(16) __nv_bfloat16 g_yh[NE], g_yl[NE];
__device__ __align__(16) __nv_bfloat16 g_kth[NE], g_ktl[NE];   // [512, 16384]
__device__ __align__(16) __nv_bfloat16 g_vth[NE], g_vtl[NE];
__device__ __align__(16) __nv_bfloat16 g_wth[(size_t)4 * DIMD * DIMD];
__device__ __align__(16) __nv_bfloat16 g_wtl[(size_t)4 * DIMD * DIMD];
__device__ __align__(16) __nv_bfloat16 g_ph[STN], g_pl[STN];
__device__ __align__(16) __nv_bfloat16 g_sch[SCN], g_scl[SCN];
__device__ __align__(16) float g_st[STN];
__device__ __align__(16) float g_yf[NE];

// ---------------------------------------------------------------------------
// helpers
// ---------------------------------------------------------------------------
__device__ __forceinline__ uint32_t smem_u32(const void* p) {
    uint32_t a;
    asm("{ .reg .u64 t; cvta.to.shared.u64 t, %1; cvt.u32.u64 %0, t; }" : "=r"(a) : "l"(p));
    return a;
}
__device__ __forceinline__ void cp16(uint32_t dst, const void* src) {
    asm volatile("cp.async.cg.shared.global [%0], [%1], 16;" :: "r"(dst), "l"(src));
}
#define CP_COMMIT() asm volatile("cp.async.commit_group;" ::: "memory")
template <int N> __device__ __forceinline__ void cp_wait() {
    asm volatile("cp.async.wait_group %0;" :: "n"(N) : "memory");
}
__device__ __forceinline__ void ldm4(uint32_t* r, uint32_t addr) {
    asm volatile("ldmatrix.sync.aligned.m8n8.x4.shared.b16 {%0,%1,%2,%3}, [%4];"
                 : "=r"(r[0]), "=r"(r[1]), "=r"(r[2]), "=r"(r[3]) : "r"(addr));
}
__device__ __forceinline__ void mma16816(float* d, const uint32_t* a, uint32_t b0, uint32_t b1) {
    asm volatile("mma.sync.aligned.m16n8k16.row.col.f32.bf16.bf16.f32 "
                 "{%0,%1,%2,%3},{%4,%5,%6,%7},{%8,%9},{%0,%1,%2,%3};"
                 : "+f"(d[0]), "+f"(d[1]), "+f"(d[2]), "+f"(d[3])
                 : "r"(a[0]), "r"(a[1]), "r"(a[2]), "r"(a[3]), "r"(b0), "r"(b1));
}
// split one float into hi/lo bf16
__device__ __forceinline__ void split1(float v, uint16_t& h, uint16_t& l) {
    __nv_bfloat16 hb = __float2bfloat16(v);
    __nv_bfloat16 lb = __float2bfloat16(v - __bfloat162float(hb));
    h = __bfloat16_as_ushort(hb);
    l = __bfloat16_as_ushort(lb);
}
__device__ __forceinline__ void split2(float v0, float v1, uint32_t& hi, uint32_t& lo) {
    uint16_t h0, l0, h1, l1;
    split1(v0, h0, l0); split1(v1, h1, l1);
    hi = (uint32_t)h0 | ((uint32_t)h1 << 16);
    lo = (uint32_t)l0 | ((uint32_t)l1 << 16);
}

// ---------------------------------------------------------------------------
// warp-MMA GEMM.  C[128 x 128 tile] = sum_k A[m][k] * B[n][k]  (both K-major)
// using split-bf16 3-term products, fp32 accumulation.
// MODE 0: C = f32 (Chv)
// MODE 1: C -> hi/lo planes (Chv, Clv)
// MODE 2: like 1 but causal mask (col > row -> 0); tile is whole 128x128 chunk
// MODE 3: like 1 but adds aux (f32, same layout) before splitting
// ---------------------------------------------------------------------------
#define GSMEM 65536

template <int MODE>
__global__ __launch_bounds__(256, 1)
void gemm_mma(const __nv_bfloat16* __restrict__ Ahp, const __nv_bfloat16* __restrict__ Alp,
              long sAz, int lda,
              const __nv_bfloat16* __restrict__ Bhp, const __nv_bfloat16* __restrict__ Blp,
              long sBz, int ldb,
              void* __restrict__ Chv, void* __restrict__ Clv, long sCz, int ldc,
              const float* __restrict__ aux, int K)
{
    extern __shared__ __align__(128) char dsm[];
    const uint32_t sm = smem_u32(dsm);

    const int tid = threadIdx.x, lane = tid & 31, wid = tid >> 5;
    const int wm = wid & 1, wn = wid >> 1;          // 2 x 4 warp grid
    const long z = blockIdx.z;
    const int bm = blockIdx.y * 128, bn = blockIdx.x * 128;

    const __nv_bfloat16* Ah = Ahp + z * sAz + (long)bm * lda;
    const __nv_bfloat16* Al = Alp + z * sAz + (long)bm * lda;
    const __nv_bfloat16* Bh = Bhp + z * sBz + (long)bn * ldb;
    const __nv_bfloat16* Bl = Blp + z * sBz + (long)bn * ldb;

    float acc[4][4][4];
#pragma unroll
    for (int i = 0; i < 4; i++)
#pragma unroll
        for (int j = 0; j < 4; j++)
#pragma unroll
            for (int q = 0; q < 4; q++) acc[i][j][q] = 0.0f;

    // SMEM tile: [128 rows][8 chunks of 16B] = 16KB; chunks 0-3 hi, 4-7 lo.
    // swizzle: byte = row*128 + ((chunk ^ (row&7)) << 4)
    auto load = [&](int c, int buf) {
        const int k0 = c * 32;
        const uint32_t sb = sm + buf * 32768;
#pragma unroll
        for (int i = 0; i < 4; i++) {
            int e = tid + 256 * i;       // 0..1023
            int row = e >> 3, ch = e & 7;
            int kc = k0 + (ch & 3) * 8;
            const __nv_bfloat16* sa = (ch < 4 ? Ah : Al) + (long)row * lda + kc;
            const __nv_bfloat16* sv = (ch < 4 ? Bh : Bl) + (long)row * ldb + kc;
            uint32_t sw = (uint32_t)(row * 128 + ((ch ^ (row & 7)) << 4));
            cp16(sb + sw, sa);
            cp16(sb + 16384 + sw, sv);
        }
    };

    auto compute = [&](int buf) {
        const uint32_t ba = sm + buf * 32768;
        const uint32_t bb = ba + 16384;
#pragma unroll
        for (int kh2 = 0; kh2 < 2; kh2++) {
            uint32_t ahf[4][4], alf[4][4], bhf[2][4], blf[2][4];
#pragma unroll
            for (int mf = 0; mf < 4; mf++) {
                int row = wm * 64 + mf * 16 + (lane & 7) + ((lane >> 3) & 1) * 8;
                int ch = kh2 * 2 + (lane >> 4);
                ldm4(ahf[mf], ba + row * 128 + ((ch ^ (row & 7)) << 4));
                ldm4(alf[mf], ba + row * 128 + (((ch + 4) ^ (row & 7)) << 4));
            }
#pragma unroll
            for (int bi = 0; bi < 2; bi++) {
                int row = wn * 32 + bi * 16 + (lane & 7) + (lane >> 4) * 8;
                int ch = kh2 * 2 + ((lane >> 3) & 1);
                ldm4(bhf[bi], bb + row * 128 + ((ch ^ (row & 7)) << 4));
                ldm4(blf[bi], bb + row * 128 + (((ch + 4) ^ (row & 7)) << 4));
            }
#pragma unroll
            for (int mf = 0; mf < 4; mf++)
#pragma unroll
                for (int nf = 0; nf < 4; nf++) {
                    uint32_t b0 = bhf[nf >> 1][2 * (nf & 1)], b1 = bhf[nf >> 1][2 * (nf & 1) + 1];
                    uint32_t l0 = blf[nf >> 1][2 * (nf & 1)], l1 = blf[nf >> 1][2 * (nf & 1) + 1];
                    mma16816(acc[mf][nf], ahf[mf], b0, b1);
                    mma16816(acc[mf][nf], ahf[mf], l0, l1);
                    mma16816(acc[mf][nf], alf[mf], b0, b1);
                }
        }
    };

    const int nch = K >> 5;
    load(0, 0); CP_COMMIT();
    for (int c = 0; c < nch; c++) {
        if (c + 1 < nch) { load(c + 1, (c + 1) & 1); CP_COMMIT(); cp_wait<1>(); }
        else             { cp_wait<0>(); }
        __syncthreads();
        compute(c & 1);
        __syncthreads();
    }

    // epilogue
    const long rbase = z * sCz;
#pragma unroll
    for (int mf = 0; mf < 4; mf++) {
#pragma unroll
        for (int nf = 0; nf < 4; nf++) {
            float* d = acc[mf][nf];
            int r = bm + wm * 64 + mf * 16 + (lane >> 2);
            int c = bn + wn * 32 + nf * 8 + (lane & 3) * 2;
            long i0 = rbase + (long)r * ldc + c;
            long i1 = i0 + 8L * ldc;
            if (MODE == 0) {
                float* C = (float*)Chv;
                *(float2*)(C + i0) = make_float2(d[0], d[1]);
                *(float2*)(C + i1) = make_float2(d[2], d[3]);
            } else {
                float v0 = d[0], v1 = d[1], v2 = d[2], v3 = d[3];
                if (MODE == 2) {
                    if (c     > r)     v0 = 0.0f;
                    if (c + 1 > r)     v1 = 0.0f;
                    if (c     > r + 8) v2 = 0.0f;
                    if (c + 1 > r + 8) v3 = 0.0f;
                }
                if (MODE == 3) {
                    v0 += aux[i0]; v1 += aux[i0 + 1];
                    v2 += aux[i1]; v3 += aux[i1 + 1];
                }
                uint32_t hi0, lo0, hi1, lo1;
                split2(v0, v1, hi0, lo0);
                split2(v2, v3, hi1, lo1);
                __nv_bfloat16* Ch = (__nv_bfloat16*)Chv;
                __nv_bfloat16* Cl = (__nv_bfloat16*)Clv;
                *(uint32_t*)(Ch + i0) = hi0;
                *(uint32_t*)(Cl + i0) = lo0;
                *(uint32_t*)(Ch + i1) = hi1;
                *(uint32_t*)(Cl + i1) = lo1;
            }
        }
    }
}

// ---------------------------------------------------------------------------
// pre/post passes
// ---------------------------------------------------------------------------
__global__ __launch_bounds__(256)
void pack_split(const float4* __restrict__ in, __nv_bfloat16* __restrict__ hp,
                __nv_bfloat16* __restrict__ lp, int n4)
{
    for (int i = blockIdx.x * 256 + threadIdx.x; i < n4; i += gridDim.x * 256) {
        float4 f = in[i];
        uint32_t h0, l0, h1, l1;
        split2(f.x, f.y, h0, l0);
        split2(f.z, f.w, h1, l1);
        *(uint2*)(hp + (size_t)i * 4) = make_uint2(h0, h1);
        *(uint2*)(lp + (size_t)i * 4) = make_uint2(l0, l1);
    }
}

// transpose + split the 4 weight matrices: wt[z][n][k] = split(W_z[k][n])
__global__ __launch_bounds__(256)
void wtrans(const float* __restrict__ w0, const float* __restrict__ w1,
            const float* __restrict__ w2, const float* __restrict__ w3,
            __nv_bfloat16* __restrict__ th, __nv_bfloat16* __restrict__ tl)
{
    const float* Ws[4] = {w0, w1, w2, w3};
    const float* W = Ws[blockIdx.z];
    __shared__ float s[32][33];
    int n0 = blockIdx.x * 32, k0 = blockIdx.y * 32;
    int tx = threadIdx.x & 31, ty = threadIdx.x >> 5;
#pragma unroll
    for (int i = 0; i < 4; i++)
        s[ty + 8 * i][tx] = W[(long)(k0 + ty + 8 * i) * DIMD + n0 + tx];
    __syncthreads();
#pragma unroll
    for (int i = 0; i < 4; i++) {
        float v = s[tx][ty + 8 * i];
        uint16_t h, l;
        split1(v, h, l);
        size_t o = (size_t)blockIdx.z * DIMD * DIMD + (size_t)(n0 + ty + 8 * i) * DIMD + k0 + tx;
        ((uint16_t*)th)[o] = h;
        ((uint16_t*)tl)[o] = l;
    }
}

// bf16 plane transpose: [16384,512] -> [512,16384]
__global__ __launch_bounds__(256)
void utrans(const __nv_bfloat16* __restrict__ in, __nv_bfloat16* __restrict__ out)
{
    __shared__ __nv_bfloat16 s[32][33];
    int c0 = blockIdx.x * 32, r0 = blockIdx.y * 32;
    int tx = threadIdx.x & 31, ty = threadIdx.x >> 5;
#pragma unroll
    for (int i = 0; i < 4; i++)
        s[ty + 8 * i][tx] = in[(size_t)(r0 + ty + 8 * i) * DIMD + c0 + tx];
    __syncthreads();
#pragma unroll
    for (int i = 0; i < 4; i++)
        out[(size_t)(c0 + ty + 8 * i) * ROWS_TOTAL + r0 + tx] = s[tx][ty + 8 * i];
}

// exclusive prefix over chunks within each batch; f32 state -> hi/lo planes
__global__ __launch_bounds__(256)
void prefix_split(const float* __restrict__ st, __nv_bfloat16* __restrict__ ph,
                  __nv_bfloat16* __restrict__ pl)
{
    const int e = blockIdx.x * 256 + threadIdx.x;   // [0, 512*512)
    const int b = blockIdx.y;
    float run = 0.0f;
    for (int c = 0; c < CHUNKS_PER_BATCH; c++) {
        size_t idx = ((size_t)(b * CHUNKS_PER_BATCH + c)) * ((size_t)DIMD * DIMD) + e;
        uint16_t h, l;
        split1(run, h, l);
        ((uint16_t*)ph)[idx] = h;
        ((uint16_t*)pl)[idx] = l;
        run += st[idx];
    }
}

// ---------------------------------------------------------------------------
// launcher
// ---------------------------------------------------------------------------
extern "C" void kernel_launch(void* const* d_in, const int* in_sizes, int n_in,
                              void* d_out, int out_size)
{
    int xi = 0;
    for (int i = 0; i < n_in; i++)
        if (in_sizes[i] == (int)(ROWS_TOTAL * DIMD)) { xi = i; break; }
    const float* W[4]; int wi = 0;
    for (int i = 0; i < n_in && wi < 4; i++) { if (i == xi) continue; W[wi++] = (const float*)d_in[i]; }
    const float* x = (const float*)d_in[xi];

    __nv_bfloat16 *xh, *xl, *qh, *ql, *kh, *kl, *vh, *vl, *yh, *yl;
    __nv_bfloat16 *kth, *ktl, *vth, *vtl, *wth, *wtl, *ph, *pl, *sch, *scl;
    float *st, *yf;
    cudaGetSymbolAddress((void**)&xh, g_xh);   cudaGetSymbolAddress((void**)&xl, g_xl);
    cudaGetSymbolAddress((void**)&qh, g_qh);   cudaGetSymbolAddress((void**)&ql, g_ql);
    cudaGetSymbolAddress((void**)&kh, g_kh);   cudaGetSymbolAddress((void**)&kl, g_kl);
    cudaGetSymbolAddress((void**)&vh, g_vh);   cudaGetSymbolAddress((void**)&vl, g_vl);
    cudaGetSymbolAddress((void**)&yh, g_yh);   cudaGetSymbolAddress((void**)&yl, g_yl);
    cudaGetSymbolAddress((void**)&kth, g_kth); cudaGetSymbolAddress((void**)&ktl, g_ktl);
    cudaGetSymbolAddress((void**)&vth, g_vth); cudaGetSymbolAddress((void**)&vtl, g_vtl);
    cudaGetSymbolAddress((void**)&wth, g_wth); cudaGetSymbolAddress((void**)&wtl, g_wtl);
    cudaGetSymbolAddress((void**)&ph, g_ph);   cudaGetSymbolAddress((void**)&pl, g_pl);
    cudaGetSymbolAddress((void**)&sch, g_sch); cudaGetSymbolAddress((void**)&scl, g_scl);
    cudaGetSymbolAddress((void**)&st, g_st);   cudaGetSymbolAddress((void**)&yf, g_yf);

    cudaFuncSetAttribute(gemm_mma<0>, cudaFuncAttributeMaxDynamicSharedMemorySize, GSMEM);
    cudaFuncSetAttribute(gemm_mma<1>, cudaFuncAttributeMaxDynamicSharedMemorySize, GSMEM);
    cudaFuncSetAttribute(gemm_mma<2>, cudaFuncAttributeMaxDynamicSharedMemorySize, GSMEM);
    cudaFuncSetAttribute(gemm_mma<3>, cudaFuncAttributeMaxDynamicSharedMemorySize, GSMEM);

    const long CH = (long)CCHUNK * DIMD;   // 65536
    const long ST = (long)DIMD * DIMD;     // 262144
    const long SS = (long)CCHUNK * CCHUNK; // 16384

    // pack x into hi/lo planes; transpose+split weights
    pack_split<<<4096, 256>>>((const float4*)x, xh, xl, (int)(NE / 4));
    wtrans<<<dim3(16, 16, 4), 256>>>(W[0], W[1], W[2], W[3], wth, wtl);

    // q/k/v projections (M=16384, N=512, K=512) -> split planes
    gemm_mma<1><<<dim3(4, 128, 1), 256, GSMEM>>>(xh, xl, 0, DIMD, wth + 0 * ST, wtl + 0 * ST, 0, DIMD,
                                                 qh, ql, 0, DIMD, nullptr, DIMD);
    gemm_mma<1><<<dim3(4, 128, 1), 256, GSMEM>>>(xh, xl, 0, DIMD, wth + 1 * ST, wtl + 1 * ST, 0, DIMD,
                                                 kh, kl, 0, DIMD, nullptr, DIMD);
    gemm_mma<1><<<dim3(4, 128, 1), 256, GSMEM>>>(xh, xl, 0, DIMD, wth + 2 * ST, wtl + 2 * ST, 0, DIMD,
                                                 vh, vl, 0, DIMD, nullptr, DIMD);

    // transposed k, v planes
    utrans<<<dim3(16, 512), 256>>>(kh, kth);
    utrans<<<dim3(16, 512), 256>>>(kl, ktl);
    utrans<<<dim3(16, 512), 256>>>(vh, vth);
    utrans<<<dim3(16, 512), 256>>>(vl, vtl);

    // per-chunk state S_c = V_c^T K_c (f32), z = chunk
    gemm_mma<0><<<dim3(4, 4, NCHUNKS), 256, GSMEM>>>(vth, vtl, 128, ROWS_TOTAL,
                                                     kth, ktl, 128, ROWS_TOTAL,
                                                     st, nullptr, ST, DIMD, nullptr, CCHUNK);
    // exclusive prefix -> P planes
    prefix_split<<<dim3((unsigned)(ST / 256), 4), 256>>>(st, ph, pl);

    // inter-chunk: yf = Q_c @ P_c^T (f32)
    gemm_mma<0><<<dim3(4, 1, NCHUNKS), 256, GSMEM>>>(qh, ql, CH, DIMD,
                                                     ph, pl, ST, DIMD,
                                                     yf, nullptr, CH, DIMD, nullptr, DIMD);
    // intra-chunk masked scores -> split planes
    gemm_mma<2><<<dim3(1, 1, NCHUNKS), 256, GSMEM>>>(qh, ql, CH, DIMD,
                                                     kh, kl, CH, DIMD,
                                                     sch, scl, SS, CCHUNK, nullptr, DIMD);
    // y = split(scores @ V_c + yf)
    gemm_mma<3><<<dim3(4, 1, NCHUNKS), 256, GSMEM>>>(sch, scl, SS, CCHUNK,
                                                     vth, vtl, 128, ROWS_TOTAL,
                                                     yh, yl, CH, DIMD, yf, CCHUNK);
    // out = y @ Wo (f32)
    gemm_mma<0><<<dim3(4, 128, 1), 256, GSMEM>>>(yh, yl, 0, DIMD, wth + 3 * ST, wtl + 3 * ST, 0, DIMD,
                                                 d_out, nullptr, 0, DIMD, nullptr, DIMD);
}

// round 4
// speedup vs baseline: 3.6540x; 1.0694x over previous
#include <cuda_runtime.h>
#include <cuda_bf16.h>
#include <cstdint>
#include <cstddef>

// Problem constants: B=4, S=4096, D=512
#define ROWS_TOTAL 16384
#define DIMD 512
#define CCHUNK 256
#define NCHUNKS 64
#define CHUNKS_PER_BATCH 16

#define NE  ((size_t)ROWS_TOTAL * DIMD)             // 8,388,608
#define NQKV ((size_t)ROWS_TOTAL * 3 * DIMD)        // 25,165,824
#define STN ((size_t)NCHUNKS * DIMD * DIMD)         // 16,777,216
#define SCN ((size_t)NCHUNKS * CCHUNK * CCHUNK)     // 4,194,304

typedef __nv_bfloat16 bf;

// ---------------------------------------------------------------------------
// Scratch (static device globals)
// ---------------------------------------------------------------------------
__device__ __align__(16) bf g_xh[NE], g_xl[NE];
__device__ __align__(16) bf g_qkvh[NQKV], g_qkvl[NQKV];     // [16384][1536]
__device__ __align__(16) bf g_yh[NE], g_yl[NE];
__device__ __align__(16) bf g_kth[NE], g_ktl[NE];           // [512][16384]
__device__ __align__(16) bf g_vth[NE], g_vtl[NE];
__device__ __align__(16) bf g_wth[(size_t)4 * DIMD * DIMD]; // [4][512 n][512 k] = W^T
__device__ __align__(16) bf g_wtl[(size_t)4 * DIMD * DIMD];
__device__ __align__(16) bf g_ph[STN], g_pl[STN];
__device__ __align__(16) bf g_sch[SCN], g_scl[SCN];
__device__ __align__(16) float g_st[STN];

// ---------------------------------------------------------------------------
// helpers
// ---------------------------------------------------------------------------
__device__ __forceinline__ uint32_t smem_u32(const void* p) {
    uint32_t a;
    asm("{ .reg .u64 t; cvta.to.shared.u64 t, %1; cvt.u32.u64 %0, t; }" : "=r"(a) : "l"(p));
    return a;
}
__device__ __forceinline__ void cp16(uint32_t dst, const void* src) {
    asm volatile("cp.async.cg.shared.global [%0], [%1], 16;" :: "r"(dst), "l"(src));
}
#define CP_COMMIT() asm volatile("cp.async.commit_group;" ::: "memory")
template <int N> __device__ __forceinline__ void cp_wait() {
    asm volatile("cp.async.wait_group %0;" :: "n"(N) : "memory");
}
__device__ __forceinline__ void ldm4(uint32_t* r, uint32_t addr) {
    asm volatile("ldmatrix.sync.aligned.m8n8.x4.shared.b16 {%0,%1,%2,%3}, [%4];"
                 : "=r"(r[0]), "=r"(r[1]), "=r"(r[2]), "=r"(r[3]) : "r"(addr));
}
__device__ __forceinline__ void mma16816(float* d, const uint32_t* a, uint32_t b0, uint32_t b1) {
    asm volatile("mma.sync.aligned.m16n8k16.row.col.f32.bf16.bf16.f32 "
                 "{%0,%1,%2,%3},{%4,%5,%6,%7},{%8,%9},{%0,%1,%2,%3};"
                 : "+f"(d[0]), "+f"(d[1]), "+f"(d[2]), "+f"(d[3])
                 : "r"(a[0]), "r"(a[1]), "r"(a[2]), "r"(a[3]), "r"(b0), "r"(b1));
}
__device__ __forceinline__ void split1(float v, uint16_t& h, uint16_t& l) {
    __nv_bfloat16 hb = __float2bfloat16(v);
    __nv_bfloat16 lb = __float2bfloat16(v - __bfloat162float(hb));
    h = __bfloat16_as_ushort(hb);
    l = __bfloat16_as_ushort(lb);
}
__device__ __forceinline__ void split2(float v0, float v1, uint32_t& hi, uint32_t& lo) {
    uint16_t h0, l0, h1, l1;
    split1(v0, h0, l0); split1(v1, h1, l1);
    hi = (uint32_t)h0 | ((uint32_t)h1 << 16);
    lo = (uint32_t)l0 | ((uint32_t)l1 << 16);
}

// ---------------------------------------------------------------------------
// warp-MMA GEMM, CTA tile 128(M) x 256(N), 8 warps (2x4), warp tile 64x64.
// C = sum_k A1*B1^T (+ sum_k A2*B2^T if K2>0), split-bf16 3-term, fp32 accum.
// MODE 0: C f32; MODE 1: split planes; MODE 2: split planes + causal mask.
// ---------------------------------------------------------------------------
#define GSMEM 98304   // 2 buffers x (16KB A + 32KB B)

template <int MODE>
__global__ __launch_bounds__(256, 1)
void gemm2(const bf* __restrict__ A1h, const bf* __restrict__ A1l, long sA1, int lda1,
           const bf* __restrict__ B1h, const bf* __restrict__ B1l, long sB1, int ldb1, int K1,
           const bf* __restrict__ A2h, const bf* __restrict__ A2l, long sA2, int lda2,
           const bf* __restrict__ B2h, const bf* __restrict__ B2l, long sB2, int ldb2, int K2,
           void* __restrict__ Chv, void* __restrict__ Clv, long sC, int ldc)
{
    extern __shared__ __align__(128) char dsm[];
    const uint32_t sm = smem_u32(dsm);

    const int tid = threadIdx.x, lane = tid & 31, wid = tid >> 5;
    const int wm = wid & 1, wn = wid >> 1;      // 2 x 4
    const long z = blockIdx.z;
    const int bm = blockIdx.y * 128, bn = blockIdx.x * 256;

    float acc[4][8][4];
#pragma unroll
    for (int i = 0; i < 4; i++)
#pragma unroll
        for (int j = 0; j < 8; j++)
#pragma unroll
            for (int q = 0; q < 4; q++) acc[i][j][q] = 0.0f;

    // SMEM per buffer: A 128 rows x 128B (hi 64B | lo 64B), B 256 rows x 128B.
    // swizzle: byte = row*128 + ((chunk16 ^ (row&7)) << 4), chunks 0-3 hi, 4-7 lo
    auto load = [&](const bf* Ah, const bf* Al, int lda,
                    const bf* Bh, const bf* Bl, int ldb, int c, int buf) {
        const int k0 = c * 32;
        const uint32_t sb = sm + buf * 49152;
#pragma unroll
        for (int i = 0; i < 4; i++) {
            int e = tid + 256 * i;              // A: 1024 cp16
            int row = e >> 3, ch = e & 7;
            int kc = k0 + (ch & 3) * 8;
            const bf* src = (ch < 4 ? Ah : Al) + (long)row * lda + kc;
            uint32_t sw = (uint32_t)(row * 128 + ((ch ^ (row & 7)) << 4));
            cp16(sb + sw, src);
        }
#pragma unroll
        for (int i = 0; i < 8; i++) {
            int e = tid + 256 * i;              // B: 2048 cp16
            int row = e >> 3, ch = e & 7;
            int kc = k0 + (ch & 3) * 8;
            const bf* src = (ch < 4 ? Bh : Bl) + (long)row * ldb + kc;
            uint32_t sw = (uint32_t)(row * 128 + ((ch ^ (row & 7)) << 4));
            cp16(sb + 16384 + sw, src);
        }
    };

    auto compute = [&](int buf) {
        const uint32_t ba = sm + buf * 49152;
        const uint32_t bb = ba + 16384;
#pragma unroll
        for (int kh2 = 0; kh2 < 2; kh2++) {
            uint32_t ahf[4][4], alf[4][4];
#pragma unroll
            for (int mf = 0; mf < 4; mf++) {
                int row = wm * 64 + mf * 16 + (lane & 7) + ((lane >> 3) & 1) * 8;
                int ch = kh2 * 2 + (lane >> 4);
                ldm4(ahf[mf], ba + row * 128 + ((ch ^ (row & 7)) << 4));
                ldm4(alf[mf], ba + row * 128 + (((ch + 4) ^ (row & 7)) << 4));
            }
#pragma unroll
            for (int bi = 0; bi < 4; bi++) {
                uint32_t bhf[4], blf[4];
                int row = wn * 64 + bi * 16 + (lane & 7) + (lane >> 4) * 8;
                int ch = kh2 * 2 + ((lane >> 3) & 1);
                ldm4(bhf, bb + row * 128 + ((ch ^ (row & 7)) << 4));
                ldm4(blf, bb + row * 128 + (((ch + 4) ^ (row & 7)) << 4));
#pragma unroll
                for (int mf = 0; mf < 4; mf++) {
#pragma unroll
                    for (int half = 0; half < 2; half++) {
                        int nf = bi * 2 + half;
                        mma16816(acc[mf][nf], ahf[mf], bhf[2 * half], bhf[2 * half + 1]);
                        mma16816(acc[mf][nf], ahf[mf], blf[2 * half], blf[2 * half + 1]);
                        mma16816(acc[mf][nf], alf[mf], bhf[2 * half], bhf[2 * half + 1]);
                    }
                }
            }
        }
    };

    auto run = [&](const bf* Ahp, const bf* Alp, long sA, int lda,
                   const bf* Bhp, const bf* Blp, long sB, int ldb, int K) {
        const bf* Ah = Ahp + z * sA + (long)bm * lda;
        const bf* Al = Alp + z * sA + (long)bm * lda;
        const bf* Bh = Bhp + z * sB + (long)bn * ldb;
        const bf* Bl = Blp + z * sB + (long)bn * ldb;
        const int nch = K >> 5;
        load(Ah, Al, lda, Bh, Bl, ldb, 0, 0); CP_COMMIT();
        for (int c = 0; c < nch; c++) {
            if (c + 1 < nch) { load(Ah, Al, lda, Bh, Bl, ldb, c + 1, (c + 1) & 1); CP_COMMIT(); cp_wait<1>(); }
            else             { cp_wait<0>(); }
            __syncthreads();
            compute(c & 1);
            __syncthreads();
        }
    };

    run(A1h, A1l, sA1, lda1, B1h, B1l, sB1, ldb1, K1);
    if (K2 > 0) run(A2h, A2l, sA2, lda2, B2h, B2l, sB2, ldb2, K2);

    // epilogue
    const long rbase = z * sC;
#pragma unroll
    for (int mf = 0; mf < 4; mf++) {
#pragma unroll
        for (int nf = 0; nf < 8; nf++) {
            float* d = acc[mf][nf];
            int r = bm + wm * 64 + mf * 16 + (lane >> 2);
            int c = bn + wn * 64 + nf * 8 + (lane & 3) * 2;
            long i0 = rbase + (long)r * ldc + c;
            long i1 = i0 + 8L * ldc;
            if (MODE == 0) {
                float* C = (float*)Chv;
                *(float2*)(C + i0) = make_float2(d[0], d[1]);
                *(float2*)(C + i1) = make_float2(d[2], d[3]);
            } else {
                float v0 = d[0], v1 = d[1], v2 = d[2], v3 = d[3];
                if (MODE == 2) {
                    if (c     > r)     v0 = 0.0f;
                    if (c + 1 > r)     v1 = 0.0f;
                    if (c     > r + 8) v2 = 0.0f;
                    if (c + 1 > r + 8) v3 = 0.0f;
                }
                uint32_t hi0, lo0, hi1, lo1;
                split2(v0, v1, hi0, lo0);
                split2(v2, v3, hi1, lo1);
                bf* Ch = (bf*)Chv; bf* Cl = (bf*)Clv;
                *(uint32_t*)(Ch + i0) = hi0;
                *(uint32_t*)(Cl + i0) = lo0;
                *(uint32_t*)(Ch + i1) = hi1;
                *(uint32_t*)(Cl + i1) = lo1;
            }
        }
    }
}

// ---------------------------------------------------------------------------
// pre/post passes
// ---------------------------------------------------------------------------
__global__ __launch_bounds__(256)
void pack_split(const float4* __restrict__ in, bf* __restrict__ hp,
                bf* __restrict__ lp, int n4)
{
    for (int i = blockIdx.x * 256 + threadIdx.x; i < n4; i += gridDim.x * 256) {
        float4 f = in[i];
        uint32_t h0, l0, h1, l1;
        split2(f.x, f.y, h0, l0);
        split2(f.z, f.w, h1, l1);
        *(uint2*)(hp + (size_t)i * 4) = make_uint2(h0, h1);
        *(uint2*)(lp + (size_t)i * 4) = make_uint2(l0, l1);
    }
}

__global__ __launch_bounds__(256)
void wtrans(const float* __restrict__ w0, const float* __restrict__ w1,
            const float* __restrict__ w2, const float* __restrict__ w3,
            bf* __restrict__ th, bf* __restrict__ tl)
{
    const float* Ws[4] = {w0, w1, w2, w3};
    const float* W = Ws[blockIdx.z];
    __shared__ float s[32][33];
    int n0 = blockIdx.x * 32, k0 = blockIdx.y * 32;
    int tx = threadIdx.x & 31, ty = threadIdx.x >> 5;
#pragma unroll
    for (int i = 0; i < 4; i++)
        s[ty + 8 * i][tx] = W[(long)(k0 + ty + 8 * i) * DIMD + n0 + tx];
    __syncthreads();
#pragma unroll
    for (int i = 0; i < 4; i++) {
        float v = s[tx][ty + 8 * i];
        uint16_t h, l;
        split1(v, h, l);
        size_t o = (size_t)blockIdx.z * DIMD * DIMD + (size_t)(n0 + ty + 8 * i) * DIMD + k0 + tx;
        ((uint16_t*)th)[o] = h;
        ((uint16_t*)tl)[o] = l;
    }
}

// dual-plane transpose: logical in [16384][512] (row stride lds) -> out [512][16384]
__global__ __launch_bounds__(256)
void utrans2(const bf* __restrict__ inh, const bf* __restrict__ inl, int lds,
             bf* __restrict__ outh, bf* __restrict__ outl)
{
    __shared__ bf sh[32][33], sl[32][33];
    int c0 = blockIdx.x * 32, r0 = blockIdx.y * 32;
    int tx = threadIdx.x & 31, ty = threadIdx.x >> 5;
#pragma unroll
    for (int i = 0; i < 4; i++) {
        long src = (long)(r0 + ty + 8 * i) * lds + c0 + tx;
        sh[ty + 8 * i][tx] = inh[src];
        sl[ty + 8 * i][tx] = inl[src];
    }
    __syncthreads();
#pragma unroll
    for (int i = 0; i < 4; i++) {
        long dst = (long)(c0 + ty + 8 * i) * ROWS_TOTAL + r0 + tx;
        outh[dst] = sh[tx][ty + 8 * i];
        outl[dst] = sl[tx][ty + 8 * i];
    }
}

__global__ __launch_bounds__(256)
void prefix_split(const float* __restrict__ st, bf* __restrict__ ph, bf* __restrict__ pl)
{
    const int e = blockIdx.x * 256 + threadIdx.x;
    const int b = blockIdx.y;
    float run = 0.0f;
    for (int c = 0; c < CHUNKS_PER_BATCH; c++) {
        size_t idx = ((size_t)(b * CHUNKS_PER_BATCH + c)) * ((size_t)DIMD * DIMD) + e;
        uint16_t h, l;
        split1(run, h, l);
        ((uint16_t*)ph)[idx] = h;
        ((uint16_t*)pl)[idx] = l;
        run += st[idx];
    }
}

// ---------------------------------------------------------------------------
// launcher
// ---------------------------------------------------------------------------
extern "C" void kernel_launch(void* const* d_in, const int* in_sizes, int n_in,
                              void* d_out, int out_size)
{
    int xi = 0;
    for (int i = 0; i < n_in; i++)
        if (in_sizes[i] == (int)(ROWS_TOTAL * DIMD)) { xi = i; break; }
    const float* W[4]; int wi = 0;
    for (int i = 0; i < n_in && wi < 4; i++) { if (i == xi) continue; W[wi++] = (const float*)d_in[i]; }
    const float* x = (const float*)d_in[xi];

    bf *xh, *xl, *qkvh, *qkvl, *yh, *yl, *kth, *ktl, *vth, *vtl, *wth, *wtl, *ph, *pl, *sch, *scl;
    float *st;
    cudaGetSymbolAddress((void**)&xh, g_xh);     cudaGetSymbolAddress((void**)&xl, g_xl);
    cudaGetSymbolAddress((void**)&qkvh, g_qkvh); cudaGetSymbolAddress((void**)&qkvl, g_qkvl);
    cudaGetSymbolAddress((void**)&yh, g_yh);     cudaGetSymbolAddress((void**)&yl, g_yl);
    cudaGetSymbolAddress((void**)&kth, g_kth);   cudaGetSymbolAddress((void**)&ktl, g_ktl);
    cudaGetSymbolAddress((void**)&vth, g_vth);   cudaGetSymbolAddress((void**)&vtl, g_vtl);
    cudaGetSymbolAddress((void**)&wth, g_wth);   cudaGetSymbolAddress((void**)&wtl, g_wtl);
    cudaGetSymbolAddress((void**)&ph, g_ph);     cudaGetSymbolAddress((void**)&pl, g_pl);
    cudaGetSymbolAddress((void**)&sch, g_sch);   cudaGetSymbolAddress((void**)&scl, g_scl);
    cudaGetSymbolAddress((void**)&st, g_st);

    cudaFuncSetAttribute(gemm2<0>, cudaFuncAttributeMaxDynamicSharedMemorySize, GSMEM);
    cudaFuncSetAttribute(gemm2<1>, cudaFuncAttributeMaxDynamicSharedMemorySize, GSMEM);
    cudaFuncSetAttribute(gemm2<2>, cudaFuncAttributeMaxDynamicSharedMemorySize, GSMEM);

    const long ST = (long)DIMD * DIMD;            // 262144
    const long SS = (long)CCHUNK * CCHUNK;        // 65536
    const long CHQ = (long)CCHUNK * 3 * DIMD;     // 393216 (chunk stride in qkv buffer)
    const long CHY = (long)CCHUNK * DIMD;         // 131072

    // pack x; transpose+split weights (z: 0=Wq,1=Wk,2=Wv,3=Wo)
    pack_split<<<4096, 256>>>((const float4*)x, xh, xl, (int)(NE / 4));
    wtrans<<<dim3(16, 16, 4), 256>>>(W[0], W[1], W[2], W[3], wth, wtl);

    // fused q|k|v projection: [16384,1536] = x @ [Wq|Wk|Wv]   (B rows = wth z 0..2)
    gemm2<1><<<dim3(6, 128, 1), 256, GSMEM>>>(
        xh, xl, 0, DIMD, wth, wtl, 0, DIMD, DIMD,
        nullptr, nullptr, 0, 0, nullptr, nullptr, 0, 0, 0,
        qkvh, qkvl, 0, 3 * DIMD);

    // k^T, v^T (both planes per launch)
    utrans2<<<dim3(16, 512), 256>>>(qkvh + DIMD,     qkvl + DIMD,     3 * DIMD, kth, ktl);
    utrans2<<<dim3(16, 512), 256>>>(qkvh + 2 * DIMD, qkvl + 2 * DIMD, 3 * DIMD, vth, vtl);

    // per-chunk state S_c = V_c^T K_c (f32), M=512, N=512, K=256
    gemm2<0><<<dim3(2, 4, NCHUNKS), 256, GSMEM>>>(
        vth, vtl, CCHUNK, ROWS_TOTAL, kth, ktl, CCHUNK, ROWS_TOTAL, CCHUNK,
        nullptr, nullptr, 0, 0, nullptr, nullptr, 0, 0, 0,
        st, nullptr, ST, DIMD);

    // exclusive prefix over chunks -> P planes
    prefix_split<<<dim3((unsigned)(ST / 256), 4), 256>>>(st, ph, pl);

    // intra-chunk masked scores: M=256, N=256, K=512 (q vs k, both in qkv buffer)
    gemm2<2><<<dim3(1, 2, NCHUNKS), 256, GSMEM>>>(
        qkvh, qkvl, CHQ, 3 * DIMD, qkvh + DIMD, qkvl + DIMD, CHQ, 3 * DIMD, DIMD,
        nullptr, nullptr, 0, 0, nullptr, nullptr, 0, 0, 0,
        sch, scl, SS, CCHUNK);

    // fused Y_c = Q_c @ P_c^T + scores_c @ V_c  -> split planes
    gemm2<1><<<dim3(2, 2, NCHUNKS), 256, GSMEM>>>(
        qkvh, qkvl, CHQ, 3 * DIMD, ph, pl, ST, DIMD, DIMD,
        sch, scl, SS, CCHUNK, vth, vtl, CCHUNK, ROWS_TOTAL, CCHUNK,
        yh, yl, CHY, DIMD);

    // out = Y @ Wo (f32)
    gemm2<0><<<dim3(2, 128, 1), 256, GSMEM>>>(
        yh, yl, 0, DIMD, wth + 3 * ST, wtl + 3 * ST, 0, DIMD, DIMD,
        nullptr, nullptr, 0, 0, nullptr, nullptr, 0, 0, 0,
        d_out, nullptr, 0, DIMD);
}